// round 8
// baseline (speedup 1.0000x reference)
#include <cuda_runtime.h>
#include <cuda_bf16.h>

#define NN      50000
#define EE      800000
#define ET      (EE + NN)      // edges incl. self loops
#define NG      512
#define FIN     128
#define FH      64
#define NCLS    10
#define NEGS    0.2f
#define EPSV    1e-16f
#define NBLK    ((NN + 255) / 256)   // 196 scan blocks

// ---------------- device scratch (no allocations allowed) ----------------
__device__ float g_h[NN * FH];        // pre-aggregation features (fp32: precision-critical)
__device__ float g_x2[NN * FH];       // layer-1 output / layer-2 input
__device__ float g_as[NN];            // alpha_src per node
__device__ float g_ad[NN];            // alpha_dst per node
__device__ int   g_deg[NN];
__device__ int   g_off[NN + 1];
__device__ int   g_cur[NN];
__device__ int   g_csrc[ET];          // CSR (by dst): source node ids
__device__ int   g_bsum[NBLK];
__device__ float g_pool[NG * FH];
__device__ int   g_bnd[NG + 1];
__device__ int   g_is64;              // 1 if edge_index/batch are int64, else int32

// uniform-branch index load (dtype detected at runtime)
__device__ __forceinline__ int ld_idx(const void* p, long i, int is64) {
    if (is64) return (int)((const long long*)p)[i];
    return ((const int*)p)[i];
}

// ---- packed f32x2 helpers (Blackwell FFMA2: 2x fp32 throughput) ----
__device__ __forceinline__ void ffma2(unsigned long long& acc,
                                      unsigned long long a, unsigned long long b) {
    asm("fma.rn.f32x2 %0, %1, %2, %0;" : "+l"(acc) : "l"(a), "l"(b));
}
__device__ __forceinline__ void upk(unsigned long long r, float& a, float& b) {
    asm("mov.b64 {%0,%1}, %2;" : "=f"(a), "=f"(b) : "l"(r));
}

// ---------------- dtype detect: int64 vs int32 indices (1 warp) -----------
__global__ void k_detect(const void* ei) {
    const long long* p = (const long long*)ei;
    long long v = p[threadIdx.x];
    int bad = (v < 0 || v >= NN);
    unsigned m = __ballot_sync(0xffffffffu, bad);
    if (threadIdx.x == 0) g_is64 = (m == 0);
}

// ------------- fused init: deg=1, zero pool, graph boundaries -------------
__global__ void k_prep(const void* __restrict__ batch) {
    int i = blockIdx.x * blockDim.x + threadIdx.x;
    if (i < NG * FH) g_pool[i] = 0.f;
    if (i >= NN) return;
    g_deg[i] = 1;                      // self loop
    int is64 = g_is64;
    int b  = ld_idx(batch, i, is64);
    int bp = (i == 0) ? -1 : ld_idx(batch, i - 1, is64);
    for (int g = bp + 1; g <= b; g++) g_bnd[g] = i;
    if (i == NN - 1)
        for (int g = b + 1; g <= NG; g++) g_bnd[g] = NN;
}

// ---------------- degree histogram over real edges (4 edges/thread) -------
// t < HT guard: quarter q covers exactly [q*HT, (q+1)*HT) — NO overlap
// (R6/R7 bug: grid round-up made quarter tails double-process edges).
#define HT (EE / 4)            // 200000 exactly
__global__ void k_hist(const void* __restrict__ ei) {
    int t = blockIdx.x * blockDim.x + threadIdx.x;
    if (t >= HT) return;
    int is64 = g_is64;
    #pragma unroll
    for (int q = 0; q < 4; q++) {
        int e = t + q * HT;
        int d = ld_idx(ei, (long)EE + e, is64);
        atomicAdd(&g_deg[d], 1);
    }
}

// ---------------- two-kernel exclusive scan of g_deg -----------------------
// A: per-block (256) reduction -> g_bsum[blk]
__global__ void k_scanA() {
    int tid = threadIdx.x, lane = tid & 31, wid = tid >> 5;
    __shared__ int ws[8];
    int i = blockIdx.x * 256 + tid;
    int v = (i < NN) ? g_deg[i] : 0;
    #pragma unroll
    for (int off = 16; off > 0; off >>= 1) v += __shfl_xor_sync(0xffffffffu, v, off);
    if (lane == 0) ws[wid] = v;
    __syncthreads();
    if (tid == 0) {
        int s = 0;
        #pragma unroll
        for (int q = 0; q < 8; q++) s += ws[q];
        g_bsum[blockIdx.x] = s;
    }
}
// C: per-block local scan; block offset self-computed from g_bsum prefix
__global__ void k_scanC() {
    __shared__ int ws[8];
    __shared__ int boff_s;
    int tid = threadIdx.x, lane = tid & 31, wid = tid >> 5;

    // block offset = sum of g_bsum[0 .. blockIdx-1] (<=196 values, 1 per thread)
    int bv = (tid < blockIdx.x) ? g_bsum[tid] : 0;
    #pragma unroll
    for (int off = 16; off > 0; off >>= 1) bv += __shfl_xor_sync(0xffffffffu, bv, off);
    if (lane == 0) ws[wid] = bv;
    __syncthreads();
    if (tid == 0) {
        int s = 0;
        #pragma unroll
        for (int q = 0; q < 8; q++) s += ws[q];
        boff_s = s;
    }
    __syncthreads();
    int boff = boff_s;
    __syncthreads();   // ws reused below

    int i = blockIdx.x * 256 + tid;
    int v = (i < NN) ? g_deg[i] : 0;
    int val = v;
    #pragma unroll
    for (int off = 1; off < 32; off <<= 1) {
        int t = __shfl_up_sync(0xffffffffu, val, off);
        if (lane >= off) val += t;
    }
    if (lane == 31) ws[wid] = val;
    __syncthreads();
    if (wid == 0 && lane < 8) {
        int s = ws[lane];
        #pragma unroll
        for (int off = 1; off < 8; off <<= 1) {
            int t = __shfl_up_sync(0xffu, s, off);
            if (lane >= off) s += t;
        }
        ws[lane] = s;
    }
    __syncthreads();
    int woff = (wid > 0) ? ws[wid - 1] : 0;
    int excl = val - v + woff + boff;
    if (i < NN) { g_off[i] = excl; g_cur[i] = excl; }
    if (i == NN - 1) g_off[NN] = ET;   // total is a compile-time constant
}

// ---------------- scatter edges (+self loops) into CSR (4/thread) ---------
#define ST ((ET + 3) / 4)      // 212513
__global__ void k_scatter(const void* __restrict__ ei) {
    int t = blockIdx.x * blockDim.x + threadIdx.x;
    if (t >= ST) return;       // quarter q covers [q*ST, (q+1)*ST) exactly
    int is64 = g_is64;
    #pragma unroll
    for (int q = 0; q < 4; q++) {
        int i = t + q * ST;
        if (i < EE) {
            int d = ld_idx(ei, (long)EE + i, is64);
            int s = ld_idx(ei, i, is64);
            int pos = atomicAdd(&g_cur[d], 1);
            g_csrc[pos] = s;
        } else if (i < ET) {
            int n = i - EE;
            int pos = atomicAdd(&g_cur[n], 1);
            g_csrc[pos] = n;
        }
    }
}

// ---------------- linear: g_h = x @ W ; g_as = h.a_src ; g_ad = h.a_dst ----
// 128 threads, 32 nodes/block, 8 nodes/warp, packed f32x2 FMAs over K pairs.
template <int K, int SRC>
__global__ void __launch_bounds__(128) k_lin(const float* __restrict__ x,
                                             const float* __restrict__ W,
                                             const float* __restrict__ a_s,
                                             const float* __restrict__ a_d) {
    constexpr int KP = K + 4;                 // pad: (c*KP) % 32 walks banks
    __shared__ float Wt[FH * KP];             // W transposed: Wt[c][k]
    __shared__ float xs[32 * K];
    int tid = threadIdx.x;
    for (int i = tid; i < K * FH; i += 128) {
        int k = i / FH, c = i % FH;
        Wt[c * KP + k] = W[i];
    }
    int base = blockIdx.x * 32;
    const float* xin = (SRC == 0) ? x : (const float*)g_x2;
    for (int i = tid; i < 32 * K; i += 128) {
        int n = i / K;
        int node = base + n;
        xs[i] = (node < NN) ? xin[(size_t)node * K + (i % K)] : 0.f;
    }
    __syncthreads();

    int c = tid & 31;       // output cols c and c+32
    int w = tid >> 5;       // warp handles nodes base + w*8 .. +7

    unsigned long long accA[8][2], accB[8][2];
    #pragma unroll
    for (int n = 0; n < 8; n++) {
        accA[n][0] = accA[n][1] = 0ull;
        accB[n][0] = accB[n][1] = 0ull;
    }

    const ulonglong2* wrowA = (const ulonglong2*)(Wt + c * KP);
    const ulonglong2* wrowB = (const ulonglong2*)(Wt + (c + 32) * KP);
    const ulonglong2* xrow  = (const ulonglong2*)(xs + (w * 8) * K);

    #pragma unroll 4
    for (int k4 = 0; k4 < K / 4; k4++) {
        ulonglong2 wa = wrowA[k4];
        ulonglong2 wb = wrowB[k4];
        #pragma unroll
        for (int n = 0; n < 8; n++) {
            ulonglong2 xv = xrow[n * (K / 4) + k4];   // broadcast across lanes
            ffma2(accA[n][0], xv.x, wa.x);
            ffma2(accA[n][1], xv.y, wa.y);
            ffma2(accB[n][0], xv.x, wb.x);
            ffma2(accB[n][1], xv.y, wb.y);
        }
    }

    float as0 = a_s[c], as1 = a_s[32 + c];
    float ad0 = a_d[c], ad1 = a_d[32 + c];
    #pragma unroll
    for (int n = 0; n < 8; n++) {
        int node = base + w * 8 + n;
        float p0, p1, p2, p3;
        upk(accA[n][0], p0, p1); upk(accA[n][1], p2, p3);
        float h0 = (p0 + p1) + (p2 + p3);
        upk(accB[n][0], p0, p1); upk(accB[n][1], p2, p3);
        float h1 = (p0 + p1) + (p2 + p3);
        if (node < NN) {
            g_h[node * FH + c]      = h0;
            g_h[node * FH + 32 + c] = h1;
        }
        float s = h0 * as0 + h1 * as1;
        float d = h0 * ad0 + h1 * ad1;
        #pragma unroll
        for (int off = 16; off > 0; off >>= 1) {
            s += __shfl_xor_sync(0xffffffffu, s, off);
            d += __shfl_xor_sync(0xffffffffu, d, off);
        }
        if (c == 0 && node < NN) { g_as[node] = s; g_ad[node] = d; }
    }
}

// ---------------- GAT gather: warp per destination node, SINGLE pass ------
// Logits are O(±10): exp() without max-subtraction is safe in fp32 and
// mathematically identical: out = sum(e_i*h_i) / (sum e_i + EPS).
template <int LAYER>
__global__ void __launch_bounds__(256) k_gat(const float* __restrict__ b,
                                             const void* __restrict__ batch) {
    int lane = threadIdx.x & 31;
    int w = threadIdx.x >> 5;
    int node = blockIdx.x * 8 + w;        // grid exact: NN % 8 == 0
    int beg = g_off[node];
    int end = g_off[node + 1];
    float adv = g_ad[node];

    const float2* h2 = (const float2*)g_h;
    float2 acc = make_float2(0.f, 0.f);
    float esum = 0.f;
    for (int cb = beg; cb < end; cb += 32) {
        int i = cb + lane;
        int s = 0; float e = 0.f;
        if (i < end) {
            s = g_csrc[i];
            float l = g_as[s] + adv;
            l = (l > 0.f) ? l : NEGS * l;
            e = __expf(l);
        }
        esum += e;
        int cnt = min(32, end - cb);
        #pragma unroll 4
        for (int j = 0; j < cnt; j++) {
            float wj = __shfl_sync(0xffffffffu, e, j);
            int   sj = __shfl_sync(0xffffffffu, s, j);
            float2 hv = h2[sj * 32 + lane];
            acc.x = fmaf(wj, hv.x, acc.x);
            acc.y = fmaf(wj, hv.y, acc.y);
        }
    }
    #pragma unroll
    for (int off = 16; off > 0; off >>= 1)
        esum += __shfl_xor_sync(0xffffffffu, esum, off);
    float inv = 1.f / (esum + EPSV);

    float v0 = acc.x * inv + b[2 * lane];
    float v1 = acc.y * inv + b[2 * lane + 1];

    if (LAYER == 1) {
        v0 = fmaxf(v0, 0.f);
        v1 = fmaxf(v1, 0.f);
        ((float2*)g_x2)[node * 32 + lane] = make_float2(v0, v1);
    } else {
        __shared__ float sv[8][FH];
        __shared__ int sg[8];
        sv[w][2 * lane]     = v0;
        sv[w][2 * lane + 1] = v1;
        if (lane == 0) sg[w] = ld_idx(batch, node, g_is64);
        __syncthreads();
        if (threadIdx.x < FH) {
            int f = threadIdx.x;
            int g0 = sg[0];
            bool uni = true;
            #pragma unroll
            for (int q = 1; q < 8; q++) uni &= (sg[q] == g0);
            if (uni) {
                float ssum = 0.f;
                #pragma unroll
                for (int q = 0; q < 8; q++) ssum += sv[q][f];
                atomicAdd(&g_pool[g0 * FH + f], ssum);
            } else {
                #pragma unroll
                for (int q = 0; q < 8; q++)
                    atomicAdd(&g_pool[sg[q] * FH + f], sv[q][f]);
            }
        }
    }
}

// ---------------- final: mean pool -> [NG, NCLS] logits ----------------
__global__ void k_final(const float* __restrict__ Wlin, const float* __restrict__ blin,
                        float* __restrict__ out) {
    __shared__ float p[FH];
    int g = blockIdx.x, tid = threadIdx.x;
    float cnt = fmaxf((float)(g_bnd[g + 1] - g_bnd[g]), 1.0f);
    p[tid] = g_pool[g * FH + tid] / cnt;
    __syncthreads();
    if (tid < NCLS) {
        float s = blin[tid];
        #pragma unroll 8
        for (int f = 0; f < FH; f++) s = fmaf(p[f], Wlin[f * NCLS + tid], s);
        out[g * NCLS + tid] = s;
    }
}

// ---------------- launch ----------------
extern "C" void kernel_launch(void* const* d_in, const int* in_sizes, int n_in,
                              void* d_out, int out_size) {
    const float* x      = (const float*)d_in[0];
    const void*  ei     = d_in[1];
    const void*  batch  = d_in[2];
    const float* W1     = (const float*)d_in[3];
    const float* a_src1 = (const float*)d_in[4];
    const float* a_dst1 = (const float*)d_in[5];
    const float* b1     = (const float*)d_in[6];
    const float* W2     = (const float*)d_in[7];
    const float* a_src2 = (const float*)d_in[8];
    const float* a_dst2 = (const float*)d_in[9];
    const float* b2     = (const float*)d_in[10];
    const float* Wlin   = (const float*)d_in[11];
    const float* blin   = (const float*)d_in[12];
    float* out = (float*)d_out;

    // dtype detection + CSR build + graph boundaries
    k_detect <<<1, 32>>>(ei);
    k_prep   <<<(NN + 255) / 256, 256>>>(batch);
    k_hist   <<<(HT + 255) / 256, 256>>>(ei);
    k_scanA  <<<NBLK, 256>>>();
    k_scanC  <<<NBLK, 256>>>();
    k_scatter<<<(ST + 255) / 256, 256>>>(ei);

    // layer 1
    k_lin<FIN, 0><<<(NN + 31) / 32, 128>>>(x, W1, a_src1, a_dst1);
    k_gat<1>     <<<NN / 8, 256>>>(b1, batch);

    // layer 2 (+ fused mean-pool accumulation)
    k_lin<FH, 1> <<<(NN + 31) / 32, 128>>>(x, W2, a_src2, a_dst2);
    k_gat<2>     <<<NN / 8, 256>>>(b2, batch);

    // classifier head
    k_final      <<<NG, FH>>>(Wlin, blin, out);
}

// round 9
// speedup vs baseline: 1.0730x; 1.0730x over previous
#include <cuda_runtime.h>
#include <cuda_bf16.h>
#include <cuda_fp16.h>

#define NN      50000
#define EE      800000
#define ET      (EE + NN)      // edges incl. self loops
#define NG      512
#define FIN     128
#define FH      64
#define NCLS    10
#define NEGS    0.2f
#define EPSV    1e-16f
#define NBLK    ((NN + 255) / 256)   // 196 scan blocks

// ---------------- device scratch (no allocations allowed) ----------------
__device__ __half g_h[NN * FH];       // pre-aggregation features (fp16: halves gather BW;
                                      // logits/accum stay fp32 — R6/R7 fail was a scatter bug)
__device__ float g_x2[NN * FH];       // layer-1 output / layer-2 input
__device__ float g_as[NN];            // alpha_src per node
__device__ float g_ad[NN];            // alpha_dst per node
__device__ int   g_deg[NN];
__device__ int   g_off[NN + 1];
__device__ int   g_cur[NN];
__device__ int   g_csrc[ET];          // CSR (by dst): source node ids
__device__ int   g_bsum[NBLK];
__device__ float g_pool[NG * FH];
__device__ int   g_bnd[NG + 1];
__device__ int   g_is64;              // 1 if edge_index/batch are int64, else int32

// uniform-branch index load (dtype detected at runtime)
__device__ __forceinline__ int ld_idx(const void* p, long i, int is64) {
    if (is64) return (int)((const long long*)p)[i];
    return ((const int*)p)[i];
}

// ---- packed f32x2 helpers (Blackwell FFMA2: 2x fp32 throughput) ----
__device__ __forceinline__ void ffma2(unsigned long long& acc,
                                      unsigned long long a, unsigned long long b) {
    asm("fma.rn.f32x2 %0, %1, %2, %0;" : "+l"(acc) : "l"(a), "l"(b));
}
__device__ __forceinline__ void upk(unsigned long long r, float& a, float& b) {
    asm("mov.b64 {%0,%1}, %2;" : "=f"(a), "=f"(b) : "l"(r));
}

// ---------------- dtype detect: int64 vs int32 indices (1 warp) -----------
__global__ void k_detect(const void* ei) {
    const long long* p = (const long long*)ei;
    long long v = p[threadIdx.x];
    int bad = (v < 0 || v >= NN);
    unsigned m = __ballot_sync(0xffffffffu, bad);
    if (threadIdx.x == 0) g_is64 = (m == 0);
}

// ------------- fused init: deg=1, zero pool, graph boundaries -------------
__global__ void k_prep(const void* __restrict__ batch) {
    int i = blockIdx.x * blockDim.x + threadIdx.x;
    if (i < NG * FH) g_pool[i] = 0.f;
    if (i >= NN) return;
    g_deg[i] = 1;                      // self loop
    int is64 = g_is64;
    int b  = ld_idx(batch, i, is64);
    int bp = (i == 0) ? -1 : ld_idx(batch, i - 1, is64);
    for (int g = bp + 1; g <= b; g++) g_bnd[g] = i;
    if (i == NN - 1)
        for (int g = b + 1; g <= NG; g++) g_bnd[g] = NN;
}

// ---------------- degree histogram over real edges (4 edges/thread) -------
// t < HT guard: quarter q covers exactly [q*HT, (q+1)*HT) — NO overlap.
#define HT (EE / 4)            // 200000 exactly
__global__ void k_hist(const void* __restrict__ ei) {
    int t = blockIdx.x * blockDim.x + threadIdx.x;
    if (t >= HT) return;
    int is64 = g_is64;
    #pragma unroll
    for (int q = 0; q < 4; q++) {
        int e = t + q * HT;
        int d = ld_idx(ei, (long)EE + e, is64);
        atomicAdd(&g_deg[d], 1);
    }
}

// ---------------- two-kernel exclusive scan of g_deg -----------------------
__global__ void k_scanA() {
    int tid = threadIdx.x, lane = tid & 31, wid = tid >> 5;
    __shared__ int ws[8];
    int i = blockIdx.x * 256 + tid;
    int v = (i < NN) ? g_deg[i] : 0;
    #pragma unroll
    for (int off = 16; off > 0; off >>= 1) v += __shfl_xor_sync(0xffffffffu, v, off);
    if (lane == 0) ws[wid] = v;
    __syncthreads();
    if (tid == 0) {
        int s = 0;
        #pragma unroll
        for (int q = 0; q < 8; q++) s += ws[q];
        g_bsum[blockIdx.x] = s;
    }
}
__global__ void k_scanC() {
    __shared__ int ws[8];
    __shared__ int boff_s;
    int tid = threadIdx.x, lane = tid & 31, wid = tid >> 5;

    int bv = (tid < blockIdx.x) ? g_bsum[tid] : 0;
    #pragma unroll
    for (int off = 16; off > 0; off >>= 1) bv += __shfl_xor_sync(0xffffffffu, bv, off);
    if (lane == 0) ws[wid] = bv;
    __syncthreads();
    if (tid == 0) {
        int s = 0;
        #pragma unroll
        for (int q = 0; q < 8; q++) s += ws[q];
        boff_s = s;
    }
    __syncthreads();
    int boff = boff_s;
    __syncthreads();   // ws reused below

    int i = blockIdx.x * 256 + tid;
    int v = (i < NN) ? g_deg[i] : 0;
    int val = v;
    #pragma unroll
    for (int off = 1; off < 32; off <<= 1) {
        int t = __shfl_up_sync(0xffffffffu, val, off);
        if (lane >= off) val += t;
    }
    if (lane == 31) ws[wid] = val;
    __syncthreads();
    if (wid == 0 && lane < 8) {
        int s = ws[lane];
        #pragma unroll
        for (int off = 1; off < 8; off <<= 1) {
            int t = __shfl_up_sync(0xffu, s, off);
            if (lane >= off) s += t;
        }
        ws[lane] = s;
    }
    __syncthreads();
    int woff = (wid > 0) ? ws[wid - 1] : 0;
    int excl = val - v + woff + boff;
    if (i < NN) { g_off[i] = excl; g_cur[i] = excl; }
    if (i == NN - 1) g_off[NN] = ET;
}

// ---------------- scatter edges (+self loops) into CSR (4/thread) ---------
#define ST ((ET + 3) / 4)      // 212513
__global__ void k_scatter(const void* __restrict__ ei) {
    int t = blockIdx.x * blockDim.x + threadIdx.x;
    if (t >= ST) return;       // quarter q covers [q*ST, (q+1)*ST) exactly
    int is64 = g_is64;
    #pragma unroll
    for (int q = 0; q < 4; q++) {
        int i = t + q * ST;
        if (i < EE) {
            int d = ld_idx(ei, (long)EE + i, is64);
            int s = ld_idx(ei, i, is64);
            int pos = atomicAdd(&g_cur[d], 1);
            g_csrc[pos] = s;
        } else if (i < ET) {
            int n = i - EE;
            int pos = atomicAdd(&g_cur[n], 1);
            g_csrc[pos] = n;
        }
    }
}

// ---------------- linear: g_h = x @ W ; g_as = h.a_src ; g_ad = h.a_dst ----
// 128 threads, 32 nodes/block, 8 nodes/warp, packed f32x2 FMAs over K pairs.
// Compute fp32; store h as fp16 (halves gather traffic downstream).
template <int K, int SRC>
__global__ void __launch_bounds__(128) k_lin(const float* __restrict__ x,
                                             const float* __restrict__ W,
                                             const float* __restrict__ a_s,
                                             const float* __restrict__ a_d) {
    constexpr int KP = K + 4;                 // pad: (c*KP) % 32 walks banks
    __shared__ float Wt[FH * KP];             // W transposed: Wt[c][k]
    __shared__ float xs[32 * K];
    int tid = threadIdx.x;
    for (int i = tid; i < K * FH; i += 128) {
        int k = i / FH, c = i % FH;
        Wt[c * KP + k] = W[i];
    }
    int base = blockIdx.x * 32;
    const float* xin = (SRC == 0) ? x : (const float*)g_x2;
    for (int i = tid; i < 32 * K; i += 128) {
        int n = i / K;
        int node = base + n;
        xs[i] = (node < NN) ? xin[(size_t)node * K + (i % K)] : 0.f;
    }
    __syncthreads();

    int c = tid & 31;       // output cols c and c+32
    int w = tid >> 5;       // warp handles nodes base + w*8 .. +7

    unsigned long long accA[8][2], accB[8][2];
    #pragma unroll
    for (int n = 0; n < 8; n++) {
        accA[n][0] = accA[n][1] = 0ull;
        accB[n][0] = accB[n][1] = 0ull;
    }

    const ulonglong2* wrowA = (const ulonglong2*)(Wt + c * KP);
    const ulonglong2* wrowB = (const ulonglong2*)(Wt + (c + 32) * KP);
    const ulonglong2* xrow  = (const ulonglong2*)(xs + (w * 8) * K);

    #pragma unroll 4
    for (int k4 = 0; k4 < K / 4; k4++) {
        ulonglong2 wa = wrowA[k4];
        ulonglong2 wb = wrowB[k4];
        #pragma unroll
        for (int n = 0; n < 8; n++) {
            ulonglong2 xv = xrow[n * (K / 4) + k4];   // broadcast across lanes
            ffma2(accA[n][0], xv.x, wa.x);
            ffma2(accA[n][1], xv.y, wa.y);
            ffma2(accB[n][0], xv.x, wb.x);
            ffma2(accB[n][1], xv.y, wb.y);
        }
    }

    float as0 = a_s[c], as1 = a_s[32 + c];
    float ad0 = a_d[c], ad1 = a_d[32 + c];
    #pragma unroll
    for (int n = 0; n < 8; n++) {
        int node = base + w * 8 + n;
        float p0, p1, p2, p3;
        upk(accA[n][0], p0, p1); upk(accA[n][1], p2, p3);
        float h0 = (p0 + p1) + (p2 + p3);
        upk(accB[n][0], p0, p1); upk(accB[n][1], p2, p3);
        float h1 = (p0 + p1) + (p2 + p3);
        if (node < NN) {
            g_h[node * FH + c]      = __float2half_rn(h0);
            g_h[node * FH + 32 + c] = __float2half_rn(h1);
        }
        float s = h0 * as0 + h1 * as1;
        float d = h0 * ad0 + h1 * ad1;
        #pragma unroll
        for (int off = 16; off > 0; off >>= 1) {
            s += __shfl_xor_sync(0xffffffffu, s, off);
            d += __shfl_xor_sync(0xffffffffu, d, off);
        }
        if (c == 0 && node < NN) { g_as[node] = s; g_ad[node] = d; }
    }
}

// ---------------- GAT gather: warp per destination node, SINGLE pass ------
// Logits are O(±10): exp() without max-subtraction is safe in fp32 and
// mathematically identical: out = sum(e_i*h_i) / (sum e_i + EPS).
// Gathers fp16 h rows (half2/lane = 128B per edge), accumulates fp32.
template <int LAYER>
__global__ void __launch_bounds__(256) k_gat(const float* __restrict__ b,
                                             const void* __restrict__ batch) {
    int lane = threadIdx.x & 31;
    int w = threadIdx.x >> 5;
    int node = blockIdx.x * 8 + w;        // grid exact: NN % 8 == 0
    int beg = g_off[node];
    int end = g_off[node + 1];
    float adv = g_ad[node];

    const __half2* h2 = (const __half2*)g_h;
    float2 acc = make_float2(0.f, 0.f);
    float esum = 0.f;
    for (int cb = beg; cb < end; cb += 32) {
        int i = cb + lane;
        int s = 0; float e = 0.f;
        if (i < end) {
            s = g_csrc[i];
            float l = g_as[s] + adv;
            l = (l > 0.f) ? l : NEGS * l;
            e = __expf(l);
        }
        esum += e;
        int cnt = min(32, end - cb);
        #pragma unroll 4
        for (int j = 0; j < cnt; j++) {
            float wj = __shfl_sync(0xffffffffu, e, j);
            int   sj = __shfl_sync(0xffffffffu, s, j);
            float2 hv = __half22float2(h2[sj * 32 + lane]);
            acc.x = fmaf(wj, hv.x, acc.x);
            acc.y = fmaf(wj, hv.y, acc.y);
        }
    }
    #pragma unroll
    for (int off = 16; off > 0; off >>= 1)
        esum += __shfl_xor_sync(0xffffffffu, esum, off);
    float inv = 1.f / (esum + EPSV);

    float v0 = acc.x * inv + b[2 * lane];
    float v1 = acc.y * inv + b[2 * lane + 1];

    if (LAYER == 1) {
        v0 = fmaxf(v0, 0.f);
        v1 = fmaxf(v1, 0.f);
        ((float2*)g_x2)[node * 32 + lane] = make_float2(v0, v1);
    } else {
        __shared__ float sv[8][FH];
        __shared__ int sg[8];
        sv[w][2 * lane]     = v0;
        sv[w][2 * lane + 1] = v1;
        if (lane == 0) sg[w] = ld_idx(batch, node, g_is64);
        __syncthreads();
        if (threadIdx.x < FH) {
            int f = threadIdx.x;
            int g0 = sg[0];
            bool uni = true;
            #pragma unroll
            for (int q = 1; q < 8; q++) uni &= (sg[q] == g0);
            if (uni) {
                float ssum = 0.f;
                #pragma unroll
                for (int q = 0; q < 8; q++) ssum += sv[q][f];
                atomicAdd(&g_pool[g0 * FH + f], ssum);
            } else {
                #pragma unroll
                for (int q = 0; q < 8; q++)
                    atomicAdd(&g_pool[sg[q] * FH + f], sv[q][f]);
            }
        }
    }
}

// ---------------- final: mean pool -> [NG, NCLS] logits ----------------
__global__ void k_final(const float* __restrict__ Wlin, const float* __restrict__ blin,
                        float* __restrict__ out) {
    __shared__ float p[FH];
    int g = blockIdx.x, tid = threadIdx.x;
    float cnt = fmaxf((float)(g_bnd[g + 1] - g_bnd[g]), 1.0f);
    p[tid] = g_pool[g * FH + tid] / cnt;
    __syncthreads();
    if (tid < NCLS) {
        float s = blin[tid];
        #pragma unroll 8
        for (int f = 0; f < FH; f++) s = fmaf(p[f], Wlin[f * NCLS + tid], s);
        out[g * NCLS + tid] = s;
    }
}

// ---------------- launch ----------------
extern "C" void kernel_launch(void* const* d_in, const int* in_sizes, int n_in,
                              void* d_out, int out_size) {
    const float* x      = (const float*)d_in[0];
    const void*  ei     = d_in[1];
    const void*  batch  = d_in[2];
    const float* W1     = (const float*)d_in[3];
    const float* a_src1 = (const float*)d_in[4];
    const float* a_dst1 = (const float*)d_in[5];
    const float* b1     = (const float*)d_in[6];
    const float* W2     = (const float*)d_in[7];
    const float* a_src2 = (const float*)d_in[8];
    const float* a_dst2 = (const float*)d_in[9];
    const float* b2     = (const float*)d_in[10];
    const float* Wlin   = (const float*)d_in[11];
    const float* blin   = (const float*)d_in[12];
    float* out = (float*)d_out;

    // dtype detection + CSR build + graph boundaries
    k_detect <<<1, 32>>>(ei);
    k_prep   <<<(NN + 255) / 256, 256>>>(batch);
    k_hist   <<<(HT + 255) / 256, 256>>>(ei);
    k_scanA  <<<NBLK, 256>>>();
    k_scanC  <<<NBLK, 256>>>();
    k_scatter<<<(ST + 255) / 256, 256>>>(ei);

    // layer 1
    k_lin<FIN, 0><<<(NN + 31) / 32, 128>>>(x, W1, a_src1, a_dst1);
    k_gat<1>     <<<NN / 8, 256>>>(b1, batch);

    // layer 2 (+ fused mean-pool accumulation)
    k_lin<FH, 1> <<<(NN + 31) / 32, 128>>>(x, W2, a_src2, a_dst2);
    k_gat<2>     <<<NN / 8, 256>>>(b2, batch);

    // classifier head
    k_final      <<<NG, FH>>>(Wlin, blin, out);
}